// round 13
// baseline (speedup 1.0000x reference)
#include <cuda_runtime.h>
#include <cuda_bf16.h>
#include <cstdint>

// ---------------------------------------------------------------------------
// GATv2 x2 + BatchNorm GNN, GB300 (sm_103a).
// GEMM1: mma.sync bf16 2-way split, cp.async double-buffered, 128x256 tiles.
// Edge phase: flash-style fused logits + online softmax + aggregation.
// ---------------------------------------------------------------------------

#define NN     10000     // nodes
#define NPAD   10112     // 79 * 128
#define EIN    160000    // input edges
#define ETOT   170000    // + self loops
#define DIN    165
#define KPAD   192       // DIN padded to 6 chunks of 32
#define HID    1024
#define NH     8

// ----------------------------- scratch (no allocs allowed) -----------------
__device__ __nv_bfloat16 g_a_hi[NPAD * KPAD];   // BN1(x) split hi   [row][k]
__device__ __nv_bfloat16 g_a_lo[NPAD * KPAD];   // BN1(x) split lo
__device__ __nv_bfloat16 g_w_hi[2048 * KPAD];   // [Wl1|Wr1]^T hi    [n][k]
__device__ __nv_bfloat16 g_w_lo[2048 * KPAD];
__device__ float g_stat1[2 * DIN];
__device__ float g_xl1 [NN * HID];
__device__ float g_xr1 [NN * HID];
__device__ float g_h1  [NN * HID];
__device__ float g_stat2[2 * HID];
__device__ float g_h2  [NN * HID];
__device__ float g_xl2 [NN * NH];
__device__ float g_xr2 [NN * NH];
__device__ int   g_deg   [NN];
__device__ int   g_rowptr[NN + 1];
__device__ int   g_cursor[NN];
__device__ int   g_esrc  [ETOT];

__device__ __forceinline__ float leaky(float v, float s) { return v > 0.f ? v : s * v; }

__device__ __forceinline__ uint32_t smem_u32(const void* p) {
    uint32_t a;
    asm("{ .reg .u64 t; cvta.to.shared.u64 t, %1; cvt.u32.u64 %0, t; }" : "=r"(a) : "l"(p));
    return a;
}
#define CPA(dst, src) asm volatile("cp.async.cg.shared.global [%0], [%1], 16;" :: "r"(dst), "l"(src))
#define CPA_COMMIT()  asm volatile("cp.async.commit_group;" ::: "memory")
#define CPA_WAIT1()   asm volatile("cp.async.wait_group 1;" ::: "memory")
#define CPA_WAIT0()   asm volatile("cp.async.wait_group 0;" ::: "memory")

// ============================ 0) zero scratch ===============================
__global__ void k_zero()
{
    int i = blockIdx.x * blockDim.x + threadIdx.x;
    if (i < 2 * HID) g_stat2[i] = 0.f;
    if (i < NN)      g_deg[i] = 0;
}

// ============================ 1) BN1 stats ==================================
__global__ __launch_bounds__(256) void k_bn1_stats(const float* __restrict__ x)
{
    int c = blockIdx.x, t = threadIdx.x;
    float s = 0.f, q = 0.f;
    for (int r = t; r < NN; r += 256) {
        float v = x[r * DIN + c];
        s += v; q += v * v;
    }
    __shared__ float ss[256], qq[256];
    ss[t] = s; qq[t] = q; __syncthreads();
    for (int o = 128; o; o >>= 1) {
        if (t < o) { ss[t] += ss[t + o]; qq[t] += qq[t + o]; }
        __syncthreads();
    }
    if (t == 0) { g_stat1[c] = ss[0]; g_stat1[DIN + c] = qq[0]; }
}

// ============================ 2) BN1 normalize + bf16 split =================
__global__ void k_bn1_split(const float* __restrict__ x,
                            const float* __restrict__ gamma,
                            const float* __restrict__ beta)
{
    int idx = blockIdx.x * blockDim.x + threadIdx.x;
    if (idx >= NPAD * KPAD) return;
    int r = idx / KPAD;
    int k = idx - r * KPAD;
    float val = 0.f;
    if (r < NN && k < DIN) {
        float mu  = g_stat1[k] * (1.f / NN);
        float var = g_stat1[DIN + k] * (1.f / NN) - mu * mu;
        float rs  = rsqrtf(var + 1e-5f);
        val = (x[r * DIN + k] - mu) * rs * gamma[k] + beta[k];
    }
    __nv_bfloat16 hi = __float2bfloat16(val);
    __nv_bfloat16 lo = __float2bfloat16(val - __bfloat162float(hi));
    g_a_hi[idx] = hi;
    g_a_lo[idx] = lo;
}

// ============================ 2b) W transpose + split =======================
__global__ void k_wsplit(const float* __restrict__ Wl, const float* __restrict__ Wr)
{
    int idx = blockIdx.x * blockDim.x + threadIdx.x;
    if (idx >= 2048 * KPAD) return;
    int n = idx / KPAD;
    int k = idx - n * KPAD;
    float val = 0.f;
    if (k < DIN)
        val = (n < HID) ? Wl[k * HID + n] : Wr[k * HID + (n - HID)];
    __nv_bfloat16 hi = __float2bfloat16(val);
    __nv_bfloat16 lo = __float2bfloat16(val - __bfloat162float(hi));
    g_w_hi[idx] = hi;
    g_w_lo[idx] = lo;
}

// ============================ 3) GEMM1: mma.sync + cp.async =================
// CTA 128x256, 512 thr (16 warps, 4x4), warp tile 32x64.
// K: 6 chunks of 32, double-buffered. D = Ah*Bh + Ah*Bl + Al*Bh.
#define GSTRIDE 40
#define SA_BYTES (128 * GSTRIDE * 2)            // 10240
#define SB_BYTES (256 * GSTRIDE * 2)            // 20480
#define OFF_AH 0
#define OFF_AL (SA_BYTES)
#define OFF_BH (2 * SA_BYTES)
#define OFF_BL (2 * SA_BYTES + SB_BYTES)
#define BUF_BYTES (2 * SA_BYTES + 2 * SB_BYTES) // 61440
#define GEMM_SMEM (2 * BUF_BYTES)               // 122880

__device__ __forceinline__ void mma16816(float* c, const uint32_t* a, const uint32_t* b)
{
    asm volatile(
        "mma.sync.aligned.m16n8k16.row.col.f32.bf16.bf16.f32 "
        "{%0,%1,%2,%3}, {%4,%5,%6,%7}, {%8,%9}, {%0,%1,%2,%3};"
        : "+f"(c[0]), "+f"(c[1]), "+f"(c[2]), "+f"(c[3])
        : "r"(a[0]), "r"(a[1]), "r"(a[2]), "r"(a[3]), "r"(b[0]), "r"(b[1]));
}

__global__ __launch_bounds__(512) void k_gemm1_mma(const float* __restrict__ bl,
                                                   const float* __restrict__ br)
{
    extern __shared__ char smem[];
    uint32_t sbase = smem_u32(smem);
    int tid = threadIdx.x;
    int wid = tid >> 5, lane = tid & 31;
    int wr = wid & 3, wc = wid >> 2;            // 4x4 warp grid
    int qrow = lane >> 2;
    int qk   = (lane & 3) * 2;
    int row0 = blockIdx.y * 128;
    int col0 = blockIdx.x * 256;

    const __nv_bfloat16* pAh = g_a_hi + (size_t)row0 * KPAD;
    const __nv_bfloat16* pAl = g_a_lo + (size_t)row0 * KPAD;
    const __nv_bfloat16* pBh = g_w_hi + (size_t)col0 * KPAD;
    const __nv_bfloat16* pBl = g_w_lo + (size_t)col0 * KPAD;

    float acc[2][8][4];
#pragma unroll
    for (int mf = 0; mf < 2; mf++)
#pragma unroll
        for (int nf = 0; nf < 8; nf++)
#pragma unroll
            for (int j = 0; j < 4; j++) acc[mf][nf][j] = 0.f;

    // prefetch one chunk into buffer `buf`
    auto prefetch = [&](int c, int buf) {
        uint32_t b0 = sbase + buf * BUF_BYTES;
        {   // A: 512 slots (128 rows x 4 uint4), one per thread, hi+lo
            int row = tid >> 2, q = tid & 3;
            size_t go = (size_t)row * KPAD + c * 32 + q * 8;
            uint32_t so = (uint32_t)(row * GSTRIDE + q * 8) * 2;
            CPA(b0 + OFF_AH + so, pAh + go);
            CPA(b0 + OFF_AL + so, pAl + go);
        }
#pragma unroll
        for (int j = 0; j < 2; j++) {           // B: 1024 slots, hi+lo
            int flat = j * 512 + tid;
            int row = flat >> 2, q = flat & 3;
            size_t go = (size_t)row * KPAD + c * 32 + q * 8;
            uint32_t so = (uint32_t)(row * GSTRIDE + q * 8) * 2;
            CPA(b0 + OFF_BH + so, pBh + go);
            CPA(b0 + OFF_BL + so, pBl + go);
        }
    };

    prefetch(0, 0);
    CPA_COMMIT();
    int buf = 0;
    for (int c = 0; c < 6; c++) {
        if (c < 5) { prefetch(c + 1, buf ^ 1); CPA_COMMIT(); CPA_WAIT1(); }
        else       { CPA_WAIT0(); }
        __syncthreads();

        const __nv_bfloat16* Ah = (const __nv_bfloat16*)(smem + buf * BUF_BYTES + OFF_AH);
        const __nv_bfloat16* Al = (const __nv_bfloat16*)(smem + buf * BUF_BYTES + OFF_AL);
        const __nv_bfloat16* Bh = (const __nv_bfloat16*)(smem + buf * BUF_BYTES + OFF_BH);
        const __nv_bfloat16* Bl = (const __nv_bfloat16*)(smem + buf * BUF_BYTES + OFF_BL);

#pragma unroll
        for (int ks = 0; ks < 32; ks += 16) {
            uint32_t bh[8][2], blr[8][2];
#pragma unroll
            for (int nf = 0; nf < 8; nf++) {
                int n = wc * 64 + nf * 8 + qrow;
                const __nv_bfloat16* bp = Bh + n * GSTRIDE + ks + qk;
                const __nv_bfloat16* lp = Bl + n * GSTRIDE + ks + qk;
                bh[nf][0]  = *(const uint32_t*)bp;
                bh[nf][1]  = *(const uint32_t*)(bp + 8);
                blr[nf][0] = *(const uint32_t*)lp;
                blr[nf][1] = *(const uint32_t*)(lp + 8);
            }
#pragma unroll
            for (int mf = 0; mf < 2; mf++) {
                int m = wr * 32 + mf * 16 + qrow;
                const __nv_bfloat16* ap = Ah + m * GSTRIDE + ks + qk;
                const __nv_bfloat16* lp = Al + m * GSTRIDE + ks + qk;
                uint32_t ah[4], al[4];
                ah[0] = *(const uint32_t*)ap;
                ah[1] = *(const uint32_t*)(ap + 8 * GSTRIDE);
                ah[2] = *(const uint32_t*)(ap + 8);
                ah[3] = *(const uint32_t*)(ap + 8 * GSTRIDE + 8);
                al[0] = *(const uint32_t*)lp;
                al[1] = *(const uint32_t*)(lp + 8 * GSTRIDE);
                al[2] = *(const uint32_t*)(lp + 8);
                al[3] = *(const uint32_t*)(lp + 8 * GSTRIDE + 8);
#pragma unroll
                for (int nf = 0; nf < 8; nf++) {
                    mma16816(acc[mf][nf], ah, bh[nf]);
                    mma16816(acc[mf][nf], ah, blr[nf]);
                    mma16816(acc[mf][nf], al, bh[nf]);
                }
            }
        }
        __syncthreads();
        buf ^= 1;
    }

    // ---- epilogue: bias add, write xl1 / xr1 (col blocks never straddle) ----
    float* dst = (col0 < HID) ? g_xl1 : g_xr1;
    const float* bias = (col0 < HID) ? bl : br;
    int cbase = (col0 & (HID - 1)) + wc * 64;
#pragma unroll
    for (int mf = 0; mf < 2; mf++) {
        int r0 = row0 + wr * 32 + mf * 16 + qrow;
        int r1 = r0 + 8;
#pragma unroll
        for (int nf = 0; nf < 8; nf++) {
            int col = cbase + nf * 8 + qk;
            float b0 = bias[col], b1 = bias[col + 1];
            if (r0 < NN) {
                float2 v = { acc[mf][nf][0] + b0, acc[mf][nf][1] + b1 };
                *(float2*)(dst + (size_t)r0 * HID + col) = v;
            }
            if (r1 < NN) {
                float2 v = { acc[mf][nf][2] + b0, acc[mf][nf][3] + b1 };
                *(float2*)(dst + (size_t)r1 * HID + col) = v;
            }
        }
    }
}

// ============================ 4) CSR build ==================================
__global__ void k_count(const int* __restrict__ ei)
{
    int e = blockIdx.x * blockDim.x + threadIdx.x;
    if (e >= ETOT) return;
    int dst = (e < EIN) ? ei[EIN + e] : (e - EIN);
    atomicAdd(&g_deg[dst], 1);
}

__global__ __launch_bounds__(1024) void k_scan()
{
    const int CH = 10;
    int t = threadIdx.x;
    int base = t * CH;
    int local[CH]; int s = 0;
#pragma unroll
    for (int i = 0; i < CH; i++) {
        int idx = base + i;
        int v = (idx < NN) ? g_deg[idx] : 0;
        local[i] = s; s += v;
    }
    int lane = t & 31, wid = t >> 5;
    int inc = s;
#pragma unroll
    for (int o = 1; o < 32; o <<= 1) {
        int u = __shfl_up_sync(0xffffffffu, inc, o);
        if (lane >= o) inc += u;
    }
    __shared__ int wsum[32];
    if (lane == 31) wsum[wid] = inc;
    __syncthreads();
    if (wid == 0) {
        int v = wsum[lane];
#pragma unroll
        for (int o = 1; o < 32; o <<= 1) {
            int u = __shfl_up_sync(0xffffffffu, v, o);
            if (lane >= o) v += u;
        }
        wsum[lane] = v;
    }
    __syncthreads();
    int excl = inc - s + (wid > 0 ? wsum[wid - 1] : 0);
#pragma unroll
    for (int i = 0; i < CH; i++) {
        int idx = base + i;
        if (idx < NN) { g_rowptr[idx] = excl + local[i]; g_cursor[idx] = excl + local[i]; }
    }
    if (t == 1023) g_rowptr[NN] = excl + s;
}

__global__ void k_scatter(const int* __restrict__ ei)
{
    int e = blockIdx.x * blockDim.x + threadIdx.x;
    if (e >= ETOT) return;
    int src, dst;
    if (e < EIN) { src = ei[e]; dst = ei[EIN + e]; }
    else         { src = e - EIN; dst = src; }
    int pos = atomicAdd(&g_cursor[dst], 1);
    g_esrc[pos] = src;
}

// ============================ 5) L1 fused edge+softmax+aggregate ============
// one warp per node. Online-rescaled accumulators (flash-attention style):
// exactly one exp per head per edge. h1 = acc/s + bias.
__global__ __launch_bounds__(256) void k_fused1(const float* __restrict__ att,
                                                const float* __restrict__ bias)
{
    int n = (blockIdx.x * blockDim.x + threadIdx.x) >> 5;
    int lane = threadIdx.x & 31;
    if (n >= NN) return;

    const float4* pa = (const float4*)att;
    const float4* pr = (const float4*)(g_xr1 + (size_t)n * HID);
    float4 attv[NH], xrv[NH], acc[NH];
    float m[NH], s[NH];
#pragma unroll
    for (int h = 0; h < NH; h++) {
        attv[h] = pa[h * 32 + lane];
        xrv[h]  = pr[h * 32 + lane];
        acc[h]  = make_float4(0.f, 0.f, 0.f, 0.f);
        m[h] = -1e30f; s[h] = 0.f;
    }

    int beg = g_rowptr[n], end = g_rowptr[n + 1];
    for (int slot = beg; slot < end; slot++) {
        int src = g_esrc[slot];
        const float4* pl = (const float4*)(g_xl1 + (size_t)src * HID);
        float4 xlv[NH];
#pragma unroll
        for (int h = 0; h < NH; h++) xlv[h] = pl[h * 32 + lane];

#pragma unroll
        for (int h = 0; h < NH; h++) {
            float v0 = leaky(xlv[h].x + xrv[h].x, 0.2f);
            float v1 = leaky(xlv[h].y + xrv[h].y, 0.2f);
            float v2 = leaky(xlv[h].z + xrv[h].z, 0.2f);
            float v3 = leaky(xlv[h].w + xrv[h].w, 0.2f);
            float p = v0 * attv[h].x + v1 * attv[h].y + v2 * attv[h].z + v3 * attv[h].w;
#pragma unroll
            for (int o = 16; o; o >>= 1) p += __shfl_xor_sync(0xffffffffu, p, o);
            float w;
            if (p <= m[h]) {                    // max unchanged (warp-uniform)
                w = __expf(p - m[h]);
                s[h] += w;
            } else {                            // new max: w = exp(p-p) = 1
                float sc = __expf(m[h] - p);
                s[h] = s[h] * sc + 1.f;
                acc[h].x *= sc; acc[h].y *= sc; acc[h].z *= sc; acc[h].w *= sc;
                m[h] = p;
                w = 1.f;
            }
            acc[h].x += w * xlv[h].x; acc[h].y += w * xlv[h].y;
            acc[h].z += w * xlv[h].z; acc[h].w += w * xlv[h].w;
        }
    }

    float* o = g_h1 + (size_t)n * HID;
    const float4* pb = (const float4*)bias;
#pragma unroll
    for (int h = 0; h < NH; h++) {
        float is = 1.f / (s[h] + 1e-16f);
        float4 b = pb[h * 32 + lane];
        float4 v;
        v.x = acc[h].x * is + b.x; v.y = acc[h].y * is + b.y;
        v.z = acc[h].z * is + b.z; v.w = acc[h].w * is + b.w;
        ((float4*)o)[h * 32 + lane] = v;
    }
}

// ============================ 8) BN2 stats ==================================
__global__ __launch_bounds__(256) void k_bn2_stats()
{
    int r0 = blockIdx.x * 128;
    int t = threadIdx.x;
    float s[4] = {0,0,0,0}, q[4] = {0,0,0,0};
    int rmax = min(128, NN - r0);
    for (int r = 0; r < rmax; r++) {
        const float* row = g_h1 + (size_t)(r0 + r) * HID;
#pragma unroll
        for (int j = 0; j < 4; j++) {
            float v = row[t + j * 256];
            s[j] += v; q[j] += v * v;
        }
    }
#pragma unroll
    for (int j = 0; j < 4; j++) {
        atomicAdd(&g_stat2[t + j * 256], s[j]);
        atomicAdd(&g_stat2[HID + t + j * 256], q[j]);
    }
}

// ============================ 9) BN2 norm + leaky(0.01) =====================
__global__ void k_bn2_norm(const float* __restrict__ gamma,
                           const float* __restrict__ beta)
{
    int i4 = blockIdx.x * blockDim.x + threadIdx.x;
    if (i4 >= NN * HID / 4) return;
    int c4 = i4 & (HID / 4 - 1);
    float4 v = ((const float4*)g_h1)[i4];
    float4 su = ((const float4*)g_stat2)[c4];
    float4 sq = ((const float4*)(g_stat2 + HID))[c4];
    float4 gm = ((const float4*)gamma)[c4];
    float4 bt = ((const float4*)beta)[c4];
    float mu, var, rs, o;
    float4 r;
    mu = su.x * (1.f/NN); var = sq.x * (1.f/NN) - mu*mu; rs = rsqrtf(var + 1e-5f);
    o = (v.x - mu) * rs * gm.x + bt.x; r.x = leaky(o, 0.01f);
    mu = su.y * (1.f/NN); var = sq.y * (1.f/NN) - mu*mu; rs = rsqrtf(var + 1e-5f);
    o = (v.y - mu) * rs * gm.y + bt.y; r.y = leaky(o, 0.01f);
    mu = su.z * (1.f/NN); var = sq.z * (1.f/NN) - mu*mu; rs = rsqrtf(var + 1e-5f);
    o = (v.z - mu) * rs * gm.z + bt.z; r.z = leaky(o, 0.01f);
    mu = su.w * (1.f/NN); var = sq.w * (1.f/NN) - mu*mu; rs = rsqrtf(var + 1e-5f);
    o = (v.w - mu) * rs * gm.w + bt.w; r.w = leaky(o, 0.01f);
    ((float4*)g_h2)[i4] = r;
}

// ============================ 10) GEMM2 (tall-skinny) =======================
__global__ __launch_bounds__(256) void k_gemm2(const float* __restrict__ Wl,
                                               const float* __restrict__ bl,
                                               const float* __restrict__ Wr,
                                               const float* __restrict__ br)
{
    int rw = (blockIdx.x * blockDim.x + threadIdx.x) >> 5;
    int lane = threadIdx.x & 31;
    if (rw >= NN) return;
    const float* row = g_h2 + (size_t)rw * HID;
    float acc[16];
#pragma unroll
    for (int j = 0; j < 16; j++) acc[j] = 0.f;
    for (int k = lane; k < HID; k += 32) {
        float a = row[k];
        float4 w0 = ((const float4*)(Wl + k * 8))[0];
        float4 w1 = ((const float4*)(Wl + k * 8))[1];
        float4 u0 = ((const float4*)(Wr + k * 8))[0];
        float4 u1 = ((const float4*)(Wr + k * 8))[1];
        acc[0] += a*w0.x; acc[1] += a*w0.y; acc[2] += a*w0.z; acc[3] += a*w0.w;
        acc[4] += a*w1.x; acc[5] += a*w1.y; acc[6] += a*w1.z; acc[7] += a*w1.w;
        acc[8] += a*u0.x; acc[9] += a*u0.y; acc[10]+= a*u0.z; acc[11]+= a*u0.w;
        acc[12]+= a*u1.x; acc[13]+= a*u1.y; acc[14]+= a*u1.z; acc[15]+= a*u1.w;
    }
#pragma unroll
    for (int j = 0; j < 16; j++)
#pragma unroll
        for (int o = 16; o; o >>= 1)
            acc[j] += __shfl_xor_sync(0xffffffffu, acc[j], o);
    if (lane < 8)       g_xl2[rw * 8 + lane]       = acc[lane] + bl[lane];
    else if (lane < 16) g_xr2[rw * 8 + (lane - 8)] = acc[lane] + br[lane - 8];
}

// ============================ 11) L2 fused edge+softmax+aggregate ===========
// one warp per node; lanes 0..7 = heads; online (m,s,acc); head-mean at end.
__global__ __launch_bounds__(256) void k_fused2(const float* __restrict__ att,
                                                const float* __restrict__ bias2,
                                                float* __restrict__ out)
{
    int n = (blockIdx.x * blockDim.x + threadIdx.x) >> 5;
    int lane = threadIdx.x & 31;
    if (n >= NN) return;
    bool act = lane < NH;
    float a  = act ? att[lane] : 0.f;
    float xr = act ? g_xr2[n * NH + lane] : 0.f;
    float m = -1e30f, s = 0.f, acc = 0.f;
    int beg = g_rowptr[n], end = g_rowptr[n + 1];
    for (int slot = beg; slot < end; slot++) {
        int src = g_esrc[slot];
        float xl = act ? g_xl2[src * NH + lane] : 0.f;
        float lg = leaky(xl + xr, 0.2f) * a;
        float w;
        if (lg <= m) {
            w = __expf(lg - m);
            s += w;
        } else {
            float sc = __expf(m - lg);
            s = s * sc + 1.f;
            acc *= sc;
            m = lg;
            w = 1.f;
        }
        acc += w * xl;
    }
    float r = act ? acc / (s + 1e-16f) : 0.f;
#pragma unroll
    for (int o = 4; o; o >>= 1) r += __shfl_xor_sync(0xffffffffu, r, o);
    if (lane == 0) out[n] = r * 0.125f + bias2[0];
}

// ============================ launch ========================================
extern "C" void kernel_launch(void* const* d_in, const int* in_sizes, int n_in,
                              void* d_out, int out_size)
{
    const float* x      = (const float*)d_in[0];
    const float* gamma1 = (const float*)d_in[1];
    const float* beta1  = (const float*)d_in[2];
    const float* Wl1    = (const float*)d_in[3];
    const float* bl1    = (const float*)d_in[4];
    const float* Wr1    = (const float*)d_in[5];
    const float* br1    = (const float*)d_in[6];
    const float* att1   = (const float*)d_in[7];
    const float* bias1  = (const float*)d_in[8];
    const float* gamma2 = (const float*)d_in[9];
    const float* beta2  = (const float*)d_in[10];
    const float* Wl2    = (const float*)d_in[11];
    const float* bl2    = (const float*)d_in[12];
    const float* Wr2    = (const float*)d_in[13];
    const float* br2    = (const float*)d_in[14];
    const float* att2   = (const float*)d_in[15];
    const float* bias2  = (const float*)d_in[16];
    const int*   ei     = (const int*)  d_in[17];
    float* out = (float*)d_out;

    cudaFuncSetAttribute(k_gemm1_mma, cudaFuncAttributeMaxDynamicSharedMemorySize,
                         GEMM_SMEM);

    k_zero<<<(NN + 255) / 256, 256>>>();
    k_bn1_stats<<<DIN, 256>>>(x);
    k_wsplit<<<(2048 * KPAD + 255) / 256, 256>>>(Wl1, Wr1);
    k_bn1_split<<<(NPAD * KPAD + 255) / 256, 256>>>(x, gamma1, beta1);

    k_count<<<(ETOT + 255) / 256, 256>>>(ei);
    k_scan<<<1, 1024>>>();
    k_scatter<<<(ETOT + 255) / 256, 256>>>(ei);

    k_gemm1_mma<<<dim3(8, NPAD / 128), 512, GEMM_SMEM>>>(bl1, br1);

    k_fused1<<<(NN * 32 + 255) / 256, 256>>>(att1, bias1);

    k_bn2_stats<<<(NN + 127) / 128, 256>>>();
    k_bn2_norm<<<(NN * HID / 4 + 255) / 256, 256>>>(gamma2, beta2);

    k_gemm2<<<(NN * 32 + 255) / 256, 256>>>(Wl2, bl2, Wr2, br2);
    k_fused2<<<(NN * 32 + 255) / 256, 256>>>(att2, bias2, out);
}

// round 16
// speedup vs baseline: 1.2699x; 1.2699x over previous
#include <cuda_runtime.h>
#include <cuda_bf16.h>
#include <cstdint>

// ---------------------------------------------------------------------------
// GATv2 x2 + BatchNorm GNN, GB300 (sm_103a).
// GEMM1: single-pass TF32 mma.sync (m16n8k8), fp32 accumulate.
// Edge phase: R12 structure (warp-per-node logits + online (m,s); alpha inline
// in aggregation).  GEMM1 is the 4th launch so ncu profiles it.
// ---------------------------------------------------------------------------

#define NN     10000     // nodes
#define NPAD   10112     // 79 * 128
#define EIN    160000    // input edges
#define ETOT   170000    // + self loops
#define DIN    165
#define KPAD   192       // DIN padded to 6 chunks of 32
#define HID    1024
#define NH     8

// ----------------------------- scratch (no allocs allowed) -----------------
__device__ float g_xbn [NPAD * KPAD];           // BN1(x), tf32-rounded, padded
__device__ float g_wt  [2048 * KPAD];           // [Wl1|Wr1]^T, tf32-rounded
__device__ float g_stat1[2 * DIN];
__device__ float g_xl1 [NN * HID];
__device__ float g_xr1 [NN * HID];
__device__ float g_log1[ETOT * NH];             // raw logits L1
__device__ float g_ms1 [NN * 16];               // per node: m[8], s[8]
__device__ float g_h1  [NN * HID];
__device__ float g_stat2[2 * HID];
__device__ float g_h2  [NN * HID];
__device__ float g_xl2 [NN * NH];
__device__ float g_xr2 [NN * NH];
__device__ float g_log2[ETOT * NH];             // raw logits L2
__device__ float g_ms2 [NN * 16];
__device__ int   g_deg   [NN];
__device__ int   g_rowptr[NN + 1];
__device__ int   g_cursor[NN];
__device__ int   g_eidx  [ETOT];
__device__ int   g_esrc  [ETOT];

__device__ __forceinline__ float leaky(float v, float s) { return v > 0.f ? v : s * v; }

__device__ __forceinline__ float tf32r(float v) {
    uint32_t o;
    asm("cvt.rna.tf32.f32 %0, %1;" : "=r"(o) : "f"(v));
    return __uint_as_float(o);
}

// ============================ 1) W transpose (+ zero stat1) =================
// g_wt[n][k] = W[k][n]; n<1024 from Wl1, else Wr1. Also zeros g_stat1.
__global__ void k_wtr(const float* __restrict__ Wl, const float* __restrict__ Wr)
{
    int idx = blockIdx.x * blockDim.x + threadIdx.x;
    if (idx < 2 * DIN) g_stat1[idx] = 0.f;
    if (idx >= 2048 * KPAD) return;
    int n = idx / KPAD;
    int k = idx - n * KPAD;
    float val = 0.f;
    if (k < DIN)
        val = (n < HID) ? Wl[k * HID + n] : Wr[k * HID + (n - HID)];
    g_wt[idx] = tf32r(val);
}

// ============================ 2) BN1 stats (coalesced + smem bins) ==========
__global__ __launch_bounds__(256) void k_bn1_stats(const float* __restrict__ x)
{
    __shared__ float ss[DIN], qq[DIN];
    int t = threadIdx.x;
    for (int i = t; i < DIN; i += 256) { ss[i] = 0.f; qq[i] = 0.f; }
    __syncthreads();
    int stride = gridDim.x * blockDim.x;
    for (int idx = blockIdx.x * blockDim.x + t; idx < NN * DIN; idx += stride) {
        float v = x[idx];
        int c = idx % DIN;
        atomicAdd(&ss[c], v);
        atomicAdd(&qq[c], v * v);
    }
    __syncthreads();
    for (int i = t; i < DIN; i += 256) {
        atomicAdd(&g_stat1[i], ss[i]);
        atomicAdd(&g_stat1[DIN + i], qq[i]);
    }
}

// ============================ 3) BN1 normalize (tf32, padded) ===============
__global__ void k_bn1_norm(const float* __restrict__ x,
                           const float* __restrict__ gamma,
                           const float* __restrict__ beta)
{
    int idx = blockIdx.x * blockDim.x + threadIdx.x;
    if (idx >= NPAD * KPAD) return;
    int r = idx / KPAD;
    int k = idx - r * KPAD;
    float val = 0.f;
    if (r < NN && k < DIN) {
        float mu  = g_stat1[k] * (1.f / NN);
        float var = g_stat1[DIN + k] * (1.f / NN) - mu * mu;
        float rs  = rsqrtf(var + 1e-5f);
        val = (x[r * DIN + k] - mu) * rs * gamma[k] + beta[k];
    }
    g_xbn[idx] = tf32r(val);
}

// ============================ 4) GEMM1 via tf32 mma.sync ====================
// CTA 128x128, 256 thr (8 warps, 2x4), warp tile 64x32. K: 6 chunks of 32,
// 4 x m16n8k8 steps per chunk. fp32 accumulate.
#define TSTR 36   // smem row stride in f32 (32 data + 4 pad; 36 % 32 = 4)

__device__ __forceinline__ void mma1688(float* c, const uint32_t* a, const uint32_t* b)
{
    asm volatile(
        "mma.sync.aligned.m16n8k8.row.col.f32.tf32.tf32.f32 "
        "{%0,%1,%2,%3}, {%4,%5,%6,%7}, {%8,%9}, {%0,%1,%2,%3};"
        : "+f"(c[0]), "+f"(c[1]), "+f"(c[2]), "+f"(c[3])
        : "r"(a[0]), "r"(a[1]), "r"(a[2]), "r"(a[3]), "r"(b[0]), "r"(b[1]));
}

__global__ __launch_bounds__(256) void k_gemm1_tf32(const float* __restrict__ bl,
                                                    const float* __restrict__ br)
{
    __shared__ __align__(16) float sA[128 * TSTR];
    __shared__ __align__(16) float sB[128 * TSTR];

    int tid = threadIdx.x;
    int wid = tid >> 5, lane = tid & 31;
    int wr = wid & 1, wc = wid >> 1;            // warp grid 2 x 4
    int qrow = lane >> 2;                       // groupID 0..7
    int tk   = lane & 3;                        // thread-in-group 0..3
    int row0 = blockIdx.y * 128;
    int col0 = blockIdx.x * 128;

    float acc[4][4][4];
#pragma unroll
    for (int mf = 0; mf < 4; mf++)
#pragma unroll
        for (int nf = 0; nf < 4; nf++)
#pragma unroll
            for (int j = 0; j < 4; j++) acc[mf][nf][j] = 0.f;

    const float* pA = g_xbn + (size_t)row0 * KPAD;
    const float* pB = g_wt  + (size_t)col0 * KPAD;

    for (int c = 0; c < 6; c++) {
        // load chunk [128 rows x 32 f32] per tile: 1024 float4, 4 per thread
#pragma unroll
        for (int i = 0; i < 4; i++) {
            int flat = i * 256 + tid;
            int row = flat >> 3, q = flat & 7;  // 8 float4 per row
            size_t go = (size_t)row * KPAD + c * 32 + q * 4;
            int so = row * TSTR + q * 4;
            *(float4*)(sA + so) = *(const float4*)(pA + go);
            *(float4*)(sB + so) = *(const float4*)(pB + go);
        }
        __syncthreads();

#pragma unroll
        for (int k8 = 0; k8 < 4; k8++) {
            int kb = k8 * 8;
            uint32_t b[4][2];
#pragma unroll
            for (int nf = 0; nf < 4; nf++) {
                int n = wc * 32 + nf * 8 + qrow;
                b[nf][0] = __float_as_uint(sB[n * TSTR + kb + tk]);
                b[nf][1] = __float_as_uint(sB[n * TSTR + kb + tk + 4]);
            }
#pragma unroll
            for (int mf = 0; mf < 4; mf++) {
                int m = wr * 64 + mf * 16 + qrow;
                uint32_t a[4];
                a[0] = __float_as_uint(sA[m * TSTR + kb + tk]);
                a[1] = __float_as_uint(sA[(m + 8) * TSTR + kb + tk]);
                a[2] = __float_as_uint(sA[m * TSTR + kb + tk + 4]);
                a[3] = __float_as_uint(sA[(m + 8) * TSTR + kb + tk + 4]);
#pragma unroll
                for (int nf = 0; nf < 4; nf++)
                    mma1688(acc[mf][nf], a, b[nf]);
            }
        }
        __syncthreads();
    }

    // ---- epilogue: bias add, write xl1 / xr1 ----
    int qk = tk * 2;
    float* dst = (col0 < HID) ? g_xl1 : g_xr1;
    const float* bias = (col0 < HID) ? bl : br;
    int cbase = (col0 & (HID - 1)) + wc * 32;
#pragma unroll
    for (int mf = 0; mf < 4; mf++) {
        int r0 = row0 + wr * 64 + mf * 16 + qrow;
        int r1 = r0 + 8;
#pragma unroll
        for (int nf = 0; nf < 4; nf++) {
            int col = cbase + nf * 8 + qk;
            float b0 = bias[col], b1 = bias[col + 1];
            if (r0 < NN) {
                float2 v = { acc[mf][nf][0] + b0, acc[mf][nf][1] + b1 };
                *(float2*)(dst + (size_t)r0 * HID + col) = v;
            }
            if (r1 < NN) {
                float2 v = { acc[mf][nf][2] + b0, acc[mf][nf][3] + b1 };
                *(float2*)(dst + (size_t)r1 * HID + col) = v;
            }
        }
    }
}

// ============================ 5) zero (stat2, deg) ==========================
__global__ void k_zero()
{
    int i = blockIdx.x * blockDim.x + threadIdx.x;
    if (i < 2 * HID) g_stat2[i] = 0.f;
    if (i < NN)      g_deg[i] = 0;
}

// ============================ 6) CSR build ==================================
__global__ void k_count(const int* __restrict__ ei)
{
    int e = blockIdx.x * blockDim.x + threadIdx.x;
    if (e >= ETOT) return;
    int dst = (e < EIN) ? ei[EIN + e] : (e - EIN);
    atomicAdd(&g_deg[dst], 1);
}

__global__ __launch_bounds__(1024) void k_scan()
{
    const int CH = 10;
    int t = threadIdx.x;
    int base = t * CH;
    int local[CH]; int s = 0;
#pragma unroll
    for (int i = 0; i < CH; i++) {
        int idx = base + i;
        int v = (idx < NN) ? g_deg[idx] : 0;
        local[i] = s; s += v;
    }
    int lane = t & 31, wid = t >> 5;
    int inc = s;
#pragma unroll
    for (int o = 1; o < 32; o <<= 1) {
        int u = __shfl_up_sync(0xffffffffu, inc, o);
        if (lane >= o) inc += u;
    }
    __shared__ int wsum[32];
    if (lane == 31) wsum[wid] = inc;
    __syncthreads();
    if (wid == 0) {
        int v = wsum[lane];
#pragma unroll
        for (int o = 1; o < 32; o <<= 1) {
            int u = __shfl_up_sync(0xffffffffu, v, o);
            if (lane >= o) v += u;
        }
        wsum[lane] = v;
    }
    __syncthreads();
    int excl = inc - s + (wid > 0 ? wsum[wid - 1] : 0);
#pragma unroll
    for (int i = 0; i < CH; i++) {
        int idx = base + i;
        if (idx < NN) { g_rowptr[idx] = excl + local[i]; g_cursor[idx] = excl + local[i]; }
    }
    if (t == 1023) g_rowptr[NN] = excl + s;
}

__global__ void k_scatter(const int* __restrict__ ei)
{
    int e = blockIdx.x * blockDim.x + threadIdx.x;
    if (e >= ETOT) return;
    int src, dst;
    if (e < EIN) { src = ei[e]; dst = ei[EIN + e]; }
    else         { src = e - EIN; dst = src; }
    int pos = atomicAdd(&g_cursor[dst], 1);
    g_eidx[pos] = e;
    g_esrc[pos] = src;
}

// ============================ 7) L1 logits + online softmax stats ===========
__global__ __launch_bounds__(256) void k_edge1(const float* __restrict__ att)
{
    int n = (blockIdx.x * blockDim.x + threadIdx.x) >> 5;
    int lane = threadIdx.x & 31;
    if (n >= NN) return;

    const float4* pa = (const float4*)att;
    const float4* pr = (const float4*)(g_xr1 + (size_t)n * HID);
    float4 attv[NH], xrv[NH];
#pragma unroll
    for (int h = 0; h < NH; h++) {
        attv[h] = pa[h * 32 + lane];
        xrv[h]  = pr[h * 32 + lane];
    }

    float m[NH], s[NH];
#pragma unroll
    for (int h = 0; h < NH; h++) { m[h] = -1e30f; s[h] = 0.f; }

    int beg = g_rowptr[n], end = g_rowptr[n + 1];
    for (int slot = beg; slot < end; slot++) {
        int src = g_esrc[slot];
        int e   = g_eidx[slot];
        const float4* pl = (const float4*)(g_xl1 + (size_t)src * HID);
        float4 xlv[NH];
#pragma unroll
        for (int h = 0; h < NH; h++) xlv[h] = pl[h * 32 + lane];

        float lg[NH];
#pragma unroll
        for (int h = 0; h < NH; h++) {
            float v0 = leaky(xlv[h].x + xrv[h].x, 0.2f);
            float v1 = leaky(xlv[h].y + xrv[h].y, 0.2f);
            float v2 = leaky(xlv[h].z + xrv[h].z, 0.2f);
            float v3 = leaky(xlv[h].w + xrv[h].w, 0.2f);
            float p = v0 * attv[h].x + v1 * attv[h].y + v2 * attv[h].z + v3 * attv[h].w;
#pragma unroll
            for (int o = 16; o; o >>= 1) p += __shfl_xor_sync(0xffffffffu, p, o);
            lg[h] = p;
            float nm = fmaxf(m[h], p);
            s[h] = s[h] * __expf(m[h] - nm) + __expf(p - nm);
            m[h] = nm;
        }
        if (lane == 0) {
            float4 L0 = { lg[0], lg[1], lg[2], lg[3] };
            float4 L1 = { lg[4], lg[5], lg[6], lg[7] };
            ((float4*)(g_log1 + (size_t)e * NH))[0] = L0;
            ((float4*)(g_log1 + (size_t)e * NH))[1] = L1;
        }
    }
    if (lane == 0) {
        float4 M0 = { m[0], m[1], m[2], m[3] };
        float4 M1 = { m[4], m[5], m[6], m[7] };
        float4 S0 = { s[0], s[1], s[2], s[3] };
        float4 S1 = { s[4], s[5], s[6], s[7] };
        float4* pm = (float4*)(g_ms1 + n * 16);
        pm[0] = M0; pm[1] = M1; pm[2] = S0; pm[3] = S1;
    }
}

// ============================ 8) aggregation L1 (alpha inline) ==============
__global__ __launch_bounds__(256) void k_agg1(const float* __restrict__ bias)
{
    int i = blockIdx.x;
    int t = threadIdx.x;
    int c0 = t * 4;
    int h = c0 >> 7;                           // uniform per warp
    float m    = g_ms1[i * 16 + h];
    float is   = 1.f / (g_ms1[i * 16 + 8 + h] + 1e-16f);
    int beg = g_rowptr[i], end = g_rowptr[i + 1];
    float4 acc = {0.f, 0.f, 0.f, 0.f};
    for (int s = beg; s < end; s++) {
        int e = g_eidx[s];
        int src = g_esrc[s];
        float al = __expf(g_log1[(size_t)e * NH + h] - m) * is;
        float4 v = *(const float4*)(g_xl1 + (size_t)src * HID + c0);
        acc.x += al * v.x; acc.y += al * v.y;
        acc.z += al * v.z; acc.w += al * v.w;
    }
    float4 b = *(const float4*)(bias + c0);
    acc.x += b.x; acc.y += b.y; acc.z += b.z; acc.w += b.w;
    *(float4*)(g_h1 + (size_t)i * HID + c0) = acc;
}

// ============================ 9) BN2 stats ==================================
__global__ __launch_bounds__(256) void k_bn2_stats()
{
    int r0 = blockIdx.x * 128;
    int t = threadIdx.x;
    float s[4] = {0,0,0,0}, q[4] = {0,0,0,0};
    int rmax = min(128, NN - r0);
    for (int r = 0; r < rmax; r++) {
        const float* row = g_h1 + (size_t)(r0 + r) * HID;
#pragma unroll
        for (int j = 0; j < 4; j++) {
            float v = row[t + j * 256];
            s[j] += v; q[j] += v * v;
        }
    }
#pragma unroll
    for (int j = 0; j < 4; j++) {
        atomicAdd(&g_stat2[t + j * 256], s[j]);
        atomicAdd(&g_stat2[HID + t + j * 256], q[j]);
    }
}

// ============================ 10) BN2 norm + leaky(0.01) ====================
__global__ void k_bn2_norm(const float* __restrict__ gamma,
                           const float* __restrict__ beta)
{
    int i4 = blockIdx.x * blockDim.x + threadIdx.x;
    if (i4 >= NN * HID / 4) return;
    int c4 = i4 & (HID / 4 - 1);
    float4 v = ((const float4*)g_h1)[i4];
    float4 su = ((const float4*)g_stat2)[c4];
    float4 sq = ((const float4*)(g_stat2 + HID))[c4];
    float4 gm = ((const float4*)gamma)[c4];
    float4 bt = ((const float4*)beta)[c4];
    float mu, var, rs, o;
    float4 r;
    mu = su.x * (1.f/NN); var = sq.x * (1.f/NN) - mu*mu; rs = rsqrtf(var + 1e-5f);
    o = (v.x - mu) * rs * gm.x + bt.x; r.x = leaky(o, 0.01f);
    mu = su.y * (1.f/NN); var = sq.y * (1.f/NN) - mu*mu; rs = rsqrtf(var + 1e-5f);
    o = (v.y - mu) * rs * gm.y + bt.y; r.y = leaky(o, 0.01f);
    mu = su.z * (1.f/NN); var = sq.z * (1.f/NN) - mu*mu; rs = rsqrtf(var + 1e-5f);
    o = (v.z - mu) * rs * gm.z + bt.z; r.z = leaky(o, 0.01f);
    mu = su.w * (1.f/NN); var = sq.w * (1.f/NN) - mu*mu; rs = rsqrtf(var + 1e-5f);
    o = (v.w - mu) * rs * gm.w + bt.w; r.w = leaky(o, 0.01f);
    ((float4*)g_h2)[i4] = r;
}

// ============================ 11) GEMM2 (tall-skinny) =======================
__global__ __launch_bounds__(256) void k_gemm2(const float* __restrict__ Wl,
                                               const float* __restrict__ bl,
                                               const float* __restrict__ Wr,
                                               const float* __restrict__ br)
{
    int rw = (blockIdx.x * blockDim.x + threadIdx.x) >> 5;
    int lane = threadIdx.x & 31;
    if (rw >= NN) return;
    const float* row = g_h2 + (size_t)rw * HID;
    float acc[16];
#pragma unroll
    for (int j = 0; j < 16; j++) acc[j] = 0.f;
    for (int k = lane; k < HID; k += 32) {
        float a = row[k];
        float4 w0 = ((const float4*)(Wl + k * 8))[0];
        float4 w1 = ((const float4*)(Wl + k * 8))[1];
        float4 u0 = ((const float4*)(Wr + k * 8))[0];
        float4 u1 = ((const float4*)(Wr + k * 8))[1];
        acc[0] += a*w0.x; acc[1] += a*w0.y; acc[2] += a*w0.z; acc[3] += a*w0.w;
        acc[4] += a*w1.x; acc[5] += a*w1.y; acc[6] += a*w1.z; acc[7] += a*w1.w;
        acc[8] += a*u0.x; acc[9] += a*u0.y; acc[10]+= a*u0.z; acc[11]+= a*u0.w;
        acc[12]+= a*u1.x; acc[13]+= a*u1.y; acc[14]+= a*u1.z; acc[15]+= a*u1.w;
    }
#pragma unroll
    for (int j = 0; j < 16; j++)
#pragma unroll
        for (int o = 16; o; o >>= 1)
            acc[j] += __shfl_xor_sync(0xffffffffu, acc[j], o);
    if (lane < 8)       g_xl2[rw * 8 + lane]       = acc[lane] + bl[lane];
    else if (lane < 16) g_xr2[rw * 8 + (lane - 8)] = acc[lane] + br[lane - 8];
}

// ============================ 12) L2 logits + online stats ==================
__global__ __launch_bounds__(256) void k_edge2(const float* __restrict__ att)
{
    int n = (blockIdx.x * blockDim.x + threadIdx.x) >> 5;
    int lane = threadIdx.x & 31;
    if (n >= NN) return;
    bool act = lane < NH;
    float a  = act ? att[lane] : 0.f;
    float xr = act ? g_xr2[n * NH + lane] : 0.f;
    float m = -1e30f, s = 0.f;
    int beg = g_rowptr[n], end = g_rowptr[n + 1];
    for (int slot = beg; slot < end; slot++) {
        int src = g_esrc[slot];
        int e   = g_eidx[slot];
        if (act) {
            float xl = g_xl2[src * NH + lane];
            float lg = leaky(xl + xr, 0.2f) * a;
            g_log2[(size_t)e * NH + lane] = lg;
            float nm = fmaxf(m, lg);
            s = s * __expf(m - nm) + __expf(lg - nm);
            m = nm;
        }
    }
    if (act) {
        g_ms2[n * 16 + lane]     = m;
        g_ms2[n * 16 + 8 + lane] = s;
    }
}

// ============================ 13) aggregation L2 + head mean ================
__global__ void k_agg2(const float* __restrict__ bias2, float* __restrict__ out)
{
    int i = blockIdx.x * blockDim.x + threadIdx.x;
    if (i >= NN) return;
    float4 M0 = ((const float4*)(g_ms2 + i * 16))[0];
    float4 M1 = ((const float4*)(g_ms2 + i * 16))[1];
    float4 S0 = ((const float4*)(g_ms2 + i * 16))[2];
    float4 S1 = ((const float4*)(g_ms2 + i * 16))[3];
    float is0 = 1.f / (S0.x + 1e-16f), is1 = 1.f / (S0.y + 1e-16f);
    float is2 = 1.f / (S0.z + 1e-16f), is3 = 1.f / (S0.w + 1e-16f);
    float is4 = 1.f / (S1.x + 1e-16f), is5 = 1.f / (S1.y + 1e-16f);
    float is6 = 1.f / (S1.z + 1e-16f), is7 = 1.f / (S1.w + 1e-16f);
    int beg = g_rowptr[i], end = g_rowptr[i + 1];
    float a0 = 0, a1 = 0, a2 = 0, a3 = 0, a4 = 0, a5 = 0, a6 = 0, a7 = 0;
    for (int s = beg; s < end; s++) {
        int e = g_eidx[s];
        int src = g_esrc[s];
        float4 p0 = ((const float4*)(g_log2 + (size_t)e * NH))[0];
        float4 p1 = ((const float4*)(g_log2 + (size_t)e * NH))[1];
        float4 v0 = ((const float4*)(g_xl2 + src * NH))[0];
        float4 v1 = ((const float4*)(g_xl2 + src * NH))[1];
        a0 += __expf(p0.x - M0.x) * is0 * v0.x;
        a1 += __expf(p0.y - M0.y) * is1 * v0.y;
        a2 += __expf(p0.z - M0.z) * is2 * v0.z;
        a3 += __expf(p0.w - M0.w) * is3 * v0.w;
        a4 += __expf(p1.x - M1.x) * is4 * v1.x;
        a5 += __expf(p1.y - M1.y) * is5 * v1.y;
        a6 += __expf(p1.z - M1.z) * is6 * v1.z;
        a7 += __expf(p1.w - M1.w) * is7 * v1.w;
    }
    float s8 = (a0 + a1 + a2 + a3 + a4 + a5 + a6 + a7) * 0.125f;
    out[i] = s8 + bias2[0];
}

// ============================ launch ========================================
extern "C" void kernel_launch(void* const* d_in, const int* in_sizes, int n_in,
                              void* d_out, int out_size)
{
    const float* x      = (const float*)d_in[0];
    const float* gamma1 = (const float*)d_in[1];
    const float* beta1  = (const float*)d_in[2];
    const float* Wl1    = (const float*)d_in[3];
    const float* bl1    = (const float*)d_in[4];
    const float* Wr1    = (const float*)d_in[5];
    const float* br1    = (const float*)d_in[6];
    const float* att1   = (const float*)d_in[7];
    const float* bias1  = (const float*)d_in[8];
    const float* gamma2 = (const float*)d_in[9];
    const float* beta2  = (const float*)d_in[10];
    const float* Wl2    = (const float*)d_in[11];
    const float* bl2    = (const float*)d_in[12];
    const float* Wr2    = (const float*)d_in[13];
    const float* br2    = (const float*)d_in[14];
    const float* att2   = (const float*)d_in[15];
    const float* bias2  = (const float*)d_in[16];
    const int*   ei     = (const int*)  d_in[17];
    float* out = (float*)d_out;

    // launches 1-3: prep (wtr also zeros g_stat1 for the atomic stats pass)
    k_wtr<<<(2048 * KPAD + 255) / 256, 256>>>(Wl1, Wr1);
    k_bn1_stats<<<148, 256>>>(x);
    k_bn1_norm<<<(NPAD * KPAD + 255) / 256, 256>>>(x, gamma1, beta1);

    // launch 4: GEMM1 (profiled by ncu)
    k_gemm1_tf32<<<dim3(16, NPAD / 128), 256>>>(bl1, br1);

    k_zero<<<(NN + 255) / 256, 256>>>();
    k_count<<<(ETOT + 255) / 256, 256>>>(ei);
    k_scan<<<1, 1024>>>();
    k_scatter<<<(ETOT + 255) / 256, 256>>>(ei);

    k_edge1<<<(NN * 32 + 255) / 256, 256>>>(att1);
    k_agg1<<<NN, 256>>>(bias1);

    k_bn2_stats<<<(NN + 127) / 128, 256>>>();
    k_bn2_norm<<<(NN * HID / 4 + 255) / 256, 256>>>(gamma2, beta2);

    k_gemm2<<<(NN * 32 + 255) / 256, 256>>>(Wl2, bl2, Wr2, br2);
    k_edge2<<<(NN * 32 + 255) / 256, 256>>>(att2);
    k_agg2<<<(NN + 255) / 256, 256>>>(bias2, out);
}